// round 12
// baseline (speedup 1.0000x reference)
#include <cuda_runtime.h>
#include <cuda_bf16.h>
#include <cstdint>

#define WARPS_PER_BLOCK 4
#define NTHR (32 * WARPS_PER_BLOCK)
#define CHUNK_BYTES 2048
#define CHUNK_F4 128               // float4 per 2 KB chunk
#define CH_SLOTS 4                 // float4 per lane per chunk
#define NCHUNK 16                  // 8 head + 8 gaze per bq
#define NBUF 4                     // ring depth per warp
#define LOOKAHEAD 3

__device__ __forceinline__ float clip01(float v) { return fminf(fmaxf(v, 0.0f), 1.0f); }

__device__ __forceinline__ void mbar_init(unsigned int mbar, unsigned int count) {
    asm volatile("mbarrier.init.shared.b64 [%0], %1;" :: "r"(mbar), "r"(count) : "memory");
}
__device__ __forceinline__ void tma_issue(unsigned int dst, const void* src, unsigned int mbar) {
    asm volatile("mbarrier.arrive.expect_tx.shared.b64 _, [%0], %1;"
                 :: "r"(mbar), "r"((unsigned int)CHUNK_BYTES) : "memory");
    asm volatile("cp.async.bulk.shared::cluster.global.mbarrier::complete_tx::bytes "
                 "[%0], [%1], %2, [%3];"
                 :: "r"(dst), "l"(src), "r"((unsigned int)CHUNK_BYTES), "r"(mbar) : "memory");
}
__device__ __forceinline__ void mbar_wait(unsigned int mbar, unsigned int parity) {
    unsigned int done;
    asm volatile("{\n\t.reg .pred p;\n\t"
                 "mbarrier.try_wait.parity.acquire.cta.shared::cta.b64 p, [%1], %2;\n\t"
                 "selp.b32 %0, 1, 0, p;\n\t}"
                 : "=r"(done) : "r"(mbar), "r"(parity) : "memory");
    while (!done) {
        asm volatile("{\n\t.reg .pred p;\n\t"
                     "mbarrier.try_wait.parity.acquire.cta.shared::cta.b64 p, [%1], %2;\n\t"
                     "selp.b32 %0, 1, 0, p;\n\t}"
                     : "=r"(done) : "r"(mbar), "r"(parity) : "memory");
    }
}

__global__ __launch_bounds__(NTHR)
void gotd_eval_kernel(const float* __restrict__ G,   // gaze heatmaps   [n,64,64]
                      const float* __restrict__ H,   // head heatmaps   [n,64,64]
                      const float* __restrict__ C,   // connect heatmaps[n,64,64]
                      const float* __restrict__ W,   // watch_outside   [n]
                      float* __restrict__ out, int n)
{
    // [warp][buf][128 float4] = 4*4*2KB = 32 KB; + per-warp mbarrier quad.
    __shared__ float4 sbuf[WARPS_PER_BLOCK * NBUF * CHUNK_F4];
    __shared__ unsigned long long smbar[WARPS_PER_BLOCK * NBUF];

    const int warp = threadIdx.x >> 5;
    const int lane = threadIdx.x & 31;
    const int bq = blockIdx.x * WARPS_PER_BLOCK + warp;

    float4* wbuf = &sbuf[warp * NBUF * CHUNK_F4];
    const unsigned int sbase = (unsigned int)__cvta_generic_to_shared(wbuf);
    const unsigned int mbase = (unsigned int)__cvta_generic_to_shared(&smbar[warp * NBUF]);

    // Per-warp init only; no cross-warp coupling, no __syncthreads.
    if (lane == 0) {
#pragma unroll
        for (int b = 0; b < NBUF; b++) mbar_init(mbase + b * 8, 1);
        asm volatile("fence.proxy.async.shared::cta;" ::: "memory");
    }
    __syncwarp();
    if (bq >= n) return;

    const size_t base = (size_t)bq * 4096;
    const char* hsrc = reinterpret_cast<const char*>(H + base);
    const char* gsrc = reinterpret_cast<const char*>(G + base);

    // Chunk c: c<8 -> head bytes [c*2K,(c+1)*2K), else gaze [(c-8)*2K,...).
    auto chunk_src = [&](int c) -> const char* {
        return (c < 8) ? hsrc + c * CHUNK_BYTES : gsrc + (c - 8) * CHUNK_BYTES;
    };

    if (lane == 0) {
#pragma unroll
        for (int c = 0; c < LOOKAHEAD; c++)
            tma_issue(sbase + (c & (NBUF - 1)) * CHUNK_BYTES, chunk_src(c),
                      mbase + (c & (NBUF - 1)) * 8);
    }

    // Per-lane layout (as R3): global slot s = m*32+lane; elem idx = s*4+k;
    // row = 2*m + (lane>>4); col = (lane&15)*4+k. Chunk c holds m in [4c',4c'+4).
    float hmax = -1e30f;
    unsigned colnib = 0;
    unsigned rml = 0, rmh = 0;
    float gmax = -1e30f; int gidx = 0;

#pragma unroll
    for (int c = 0; c < NCHUNK; c++) {
        // Issue c+LOOKAHEAD BEFORE waiting on c: its buffer was consumed at
        // iter c-1, so after syncwarp it is free -> ring holds up to 4 chunks
        // in flight through the consume phase.
        if (c + LOOKAHEAD < NCHUNK) {
            __syncwarp();
            if (lane == 0) {
                asm volatile("fence.proxy.async.shared::cta;" ::: "memory");
                int cn = c + LOOKAHEAD;
                tma_issue(sbase + (cn & (NBUF - 1)) * CHUNK_BYTES, chunk_src(cn),
                          mbase + (cn & (NBUF - 1)) * 8);
            }
        }

        mbar_wait(mbase + (c & (NBUF - 1)) * 8, (c >> 2) & 1);
        const float4* buf = wbuf + (c & (NBUF - 1)) * CHUNK_F4;

        float4 v[CH_SLOTS];
#pragma unroll
        for (int i = 0; i < CH_SLOTS; i++) v[i] = buf[i * 32 + lane];

        if (c < 8) {
#pragma unroll
            for (int i = 0; i < CH_SLOTS; i++) {
                const int m = c * CH_SLOTS + i;
                float a[4] = {v[i].x, v[i].y, v[i].z, v[i].w};
                bool any5 = false;
#pragma unroll
                for (int k = 0; k < 4; k++) {
                    hmax = fmaxf(hmax, a[k]);
                    if (a[k] >= 0.5f) { colnib |= 1u << k; any5 = true; }
                }
                if (any5) {
                    int row = 2 * m + (lane >> 4);
                    if (row < 32) rml |= 1u << row; else rmh |= 1u << (row - 32);
                }
            }
        } else {
#pragma unroll
            for (int i = 0; i < CH_SLOTS; i++) {
                const int m = (c - 8) * CH_SLOTS + i;
                float a[4] = {v[i].x, v[i].y, v[i].z, v[i].w};
#pragma unroll
                for (int k = 0; k < 4; k++) {
                    // raw-value argmax; clip01 on scalar max below (inputs in
                    // [0,1): elementwise clip is identity; strict > keeps
                    // first-index semantics).
                    int idx = (m * 32 + lane) * 4 + k;
                    if (a[k] > gmax) { gmax = a[k]; gidx = idx; }
                }
            }
        }
    }

    // ---- warp-wide masks via REDUX (uniform result in all lanes) ----
    const unsigned c15 = lane & 15;
    unsigned mcl = (c15 < 8)  ? (colnib << (c15 * 4))       : 0u;
    unsigned mch = (c15 >= 8) ? (colnib << ((c15 - 8) * 4)) : 0u;
    const unsigned cl = __reduce_or_sync(0xffffffffu, mcl);
    const unsigned ch = __reduce_or_sync(0xffffffffu, mch);
    const unsigned rl = __reduce_or_sync(0xffffffffu, rml);
    const unsigned rh = __reduce_or_sync(0xffffffffu, rmh);

    // ---- butterfly reductions: every lane ends with the warp result ----
#pragma unroll
    for (int o = 16; o; o >>= 1) {
        hmax = fmaxf(hmax, __shfl_xor_sync(0xffffffffu, hmax, o));
        float gv2 = __shfl_xor_sync(0xffffffffu, gmax, o);
        int   gi2 = __shfl_xor_sync(0xffffffffu, gidx, o);
        if (gv2 > gmax || (gv2 == gmax && gi2 < gidx)) { gmax = gv2; gidx = gi2; }
    }

    // ---- bbox (rare fallback: no pixel >= 0.5 -> head peak, warp-uniform) ----
    int x1, x2, y1, y2;
    if ((cl | ch) != 0u) {
        unsigned long long cm = ((unsigned long long)ch << 32) | cl;
        unsigned long long rm = ((unsigned long long)rh << 32) | rl;
        x1 = __ffsll((long long)cm) - 1;
        x2 = 64 - __clzll((long long)cm);
        y1 = __ffsll((long long)rm) - 1;
        y2 = 64 - __clzll((long long)rm);
    } else {
        const float4* h4 = reinterpret_cast<const float4*>(H + base);
        float pv = -1e30f; int pi = 0;
#pragma unroll 4
        for (int m = 0; m < 32; m++) {
            float4 v = h4[m * 32 + lane];          // rare reload (L2-hot)
            float a[4] = {v.x, v.y, v.z, v.w};
#pragma unroll
            for (int k = 0; k < 4; k++) {
                float hv = clip01(a[k]);
                int idx = (m * 32 + lane) * 4 + k;
                if (hv > pv) { pv = hv; pi = idx; }
            }
        }
#pragma unroll
        for (int o = 16; o; o >>= 1) {
            float v2 = __shfl_xor_sync(0xffffffffu, pv, o);
            int   i2 = __shfl_xor_sync(0xffffffffu, pi, o);
            if (v2 > pv || (v2 == pv && i2 < pi)) { pv = v2; pi = i2; }
        }
        int px = pi & 63, py = pi >> 6;
        x1 = px; x2 = px + 1; y1 = py; y2 = py + 1;
    }

    // ---- epilogue (warp-uniform; 10 connect samples on lanes 0-9) ----
    const float conf_head = clip01(hmax);
    const float conf_gaze = clip01(gmax);
    const float gpx = fminf(fmaxf((float)(gidx & 63), 0.0f), 63.0f);
    const float gpy = fminf(fmaxf((float)(gidx >> 6), 0.0f), 63.0f);
    const float cx = (float)(x1 + x2) * 0.5f;
    const float cy = (float)(y1 + y2) * 0.5f;
    // jnp.round == round-half-to-even == rintf (cx/cy hit .5 exactly)
    const float hcx = fminf(fmaxf(rintf(cx), 0.0f), 63.0f);
    const float hcy = fminf(fmaxf(rintf(cy), 0.0f), 63.0f);
    const float dx = gpx - hcx, dy = gpy - hcy;
    const float stx = dx / 9.0f, sty = dy / 9.0f;   // linspace step, num=10

    float samp = 0.0f;
    if (lane < 10) {
        int xi = (int)rintf(hcx + (float)lane * stx);
        int yi = (int)rintf(hcy + (float)lane * sty);
        samp = clip01(__ldg(C + base + yi * 64 + xi));
    }
#pragma unroll
    for (int o = 16; o; o >>= 1) samp += __shfl_xor_sync(0xffffffffu, samp, o);

    if (lane == 0) {
        float norm = sqrtf(dx * dx + dy * dy);
        float dp = fminf(32.0f / norm - 1.0f, 0.0f);  // norm==0 -> +inf -> 0
        float score = samp / 10.0f + dp;
        float watch = W[bq];
        float r = (watch > 0.5f)
                ? (conf_head + (1.0f - conf_gaze) - score)
                : (conf_head + conf_gaze + score);
        out[bq] = r / 3.0f;
    }
}

extern "C" void kernel_launch(void* const* d_in, const int* in_sizes, int n_in,
                              void* d_out, int out_size) {
    const float* G = (const float*)d_in[0];  // pred_gaze_heatmap
    const float* H = (const float*)d_in[1];  // pred_head_heatmap
    const float* C = (const float*)d_in[2];  // pred_connect_heatmap
    const float* W = (const float*)d_in[3];  // pred_gaze_watch_outside
    float* out = (float*)d_out;
    int n = in_sizes[3];                     // B*Q = 8192
    int grid = (n + WARPS_PER_BLOCK - 1) / WARPS_PER_BLOCK;   // 2048
    gotd_eval_kernel<<<grid, NTHR>>>(G, H, C, W, out, n);
}

// round 13
// speedup vs baseline: 1.5003x; 1.5003x over previous
#include <cuda_runtime.h>
#include <cuda_bf16.h>
#include <cstdint>

#define WARPS_PER_BLOCK 4
#define NTHR (32 * WARPS_PER_BLOCK)
#define CHUNK_BYTES 4096
#define CHUNK_F4 256               // float4 per 4 KB chunk
#define NHCHUNK 4                  // head chunks per bq (TMA path)
#define NGBATCH 4                  // gaze reg batches per bq (LDG path)

__device__ __forceinline__ float clip01(float v) { return fminf(fmaxf(v, 0.0f), 1.0f); }

__device__ __forceinline__ void mbar_init(unsigned int mbar, unsigned int count) {
    asm volatile("mbarrier.init.shared.b64 [%0], %1;" :: "r"(mbar), "r"(count) : "memory");
}
__device__ __forceinline__ void tma_issue(unsigned int dst, const void* src, unsigned int mbar) {
    asm volatile("mbarrier.arrive.expect_tx.shared.b64 _, [%0], %1;"
                 :: "r"(mbar), "r"((unsigned int)CHUNK_BYTES) : "memory");
    asm volatile("cp.async.bulk.shared::cluster.global.mbarrier::complete_tx::bytes "
                 "[%0], [%1], %2, [%3];"
                 :: "r"(dst), "l"(src), "r"((unsigned int)CHUNK_BYTES), "r"(mbar) : "memory");
}
__device__ __forceinline__ void mbar_wait(unsigned int mbar, unsigned int parity) {
    unsigned int done;
    asm volatile("{\n\t.reg .pred p;\n\t"
                 "mbarrier.try_wait.parity.acquire.cta.shared::cta.b64 p, [%1], %2;\n\t"
                 "selp.b32 %0, 1, 0, p;\n\t}"
                 : "=r"(done) : "r"(mbar), "r"(parity) : "memory");
    while (!done) {
        asm volatile("{\n\t.reg .pred p;\n\t"
                     "mbarrier.try_wait.parity.acquire.cta.shared::cta.b64 p, [%1], %2;\n\t"
                     "selp.b32 %0, 1, 0, p;\n\t}"
                     : "=r"(done) : "r"(mbar), "r"(parity) : "memory");
    }
}

__global__ __launch_bounds__(NTHR)
void gotd_eval_kernel(const float* __restrict__ G,   // gaze heatmaps   [n,64,64]
                      const float* __restrict__ H,   // head heatmaps   [n,64,64]
                      const float* __restrict__ C,   // connect heatmaps[n,64,64]
                      const float* __restrict__ W,   // watch_outside   [n]
                      float* __restrict__ out, int n)
{
    // [warp][buf][256 float4] = 4*2*4KB = 32 KB; + per-warp mbarrier pair.
    __shared__ float4 sbuf[WARPS_PER_BLOCK * 2 * CHUNK_F4];
    __shared__ unsigned long long smbar[WARPS_PER_BLOCK * 2];

    const int warp = threadIdx.x >> 5;
    const int lane = threadIdx.x & 31;
    const int bq = blockIdx.x * WARPS_PER_BLOCK + warp;

    float4* wbuf = &sbuf[warp * 2 * CHUNK_F4];
    const unsigned int sb0 = (unsigned int)__cvta_generic_to_shared(wbuf);
    const unsigned int sb1 = sb0 + CHUNK_BYTES;
    const unsigned int mb0 = (unsigned int)__cvta_generic_to_shared(&smbar[warp * 2]);
    const unsigned int mb1 = mb0 + 8;

    // Per-warp init; no cross-warp coupling, no __syncthreads.
    if (lane == 0) {
        mbar_init(mb0, 1);
        mbar_init(mb1, 1);
        asm volatile("fence.proxy.async.shared::cta;" ::: "memory");
    }
    __syncwarp();
    if (bq >= n) return;

    const size_t base = (size_t)bq * 4096;
    const char* hsrc = reinterpret_cast<const char*>(H + base);
    const float4* g4 = reinterpret_cast<const float4*>(G + base);

    // TMA path: head chunks c = 0..3, bytes [c*4K,(c+1)*4K).
    if (lane == 0) {
        tma_issue(sb0, hsrc + 0 * CHUNK_BYTES, mb0);
        tma_issue(sb1, hsrc + 1 * CHUNK_BYTES, mb1);
    }

    // LDG path: gaze batch 0 front-issued (plain loads: R3-proven batching).
    float4 gv[8];
#pragma unroll
    for (int i = 0; i < 8; i++) gv[i] = g4[i * 32 + lane];

    // Per-lane layout (as R3): global slot s = m*32+lane; elem idx = s*4+k;
    // row = 2*m + (lane>>4); col = (lane&15)*4+k.
    float hmax = -1e30f;
    unsigned colnib = 0;
    unsigned rml = 0, rmh = 0;
    float gmax = -1e30f; int gidx = 0;

#pragma unroll
    for (int c = 0; c < NHCHUNK; c++) {
        // ---- consume head chunk c from smem (TMA) ----
        const unsigned int mb = (c & 1) ? mb1 : mb0;
        const float4* buf = wbuf + (c & 1) * CHUNK_F4;
        mbar_wait(mb, (c >> 1) & 1);

        float4 hv[8];
#pragma unroll
        for (int i = 0; i < 8; i++) hv[i] = buf[i * 32 + lane];

#pragma unroll
        for (int i = 0; i < 8; i++) {
            const int m = c * 8 + i;
            float a[4] = {hv[i].x, hv[i].y, hv[i].z, hv[i].w};
            bool any5 = false;
#pragma unroll
            for (int k = 0; k < 4; k++) {
                hmax = fmaxf(hmax, a[k]);
                if (a[k] >= 0.5f) { colnib |= 1u << k; any5 = true; }
            }
            if (any5) {
                int row = 2 * m + (lane >> 4);
                if (row < 32) rml |= 1u << row; else rmh |= 1u << (row - 32);
            }
        }

        // refill TMA pipe
        if (c + 2 < NHCHUNK) {
            __syncwarp();
            if (lane == 0) {
                asm volatile("fence.proxy.async.shared::cta;" ::: "memory");
                tma_issue((c & 1) ? sb1 : sb0, hsrc + (c + 2) * CHUNK_BYTES, mb);
            }
        }

        // ---- consume gaze batch c from registers (LDG) ----
#pragma unroll
        for (int i = 0; i < 8; i++) {
            const int m = c * 8 + i;
            float a[4] = {gv[i].x, gv[i].y, gv[i].z, gv[i].w};
#pragma unroll
            for (int k = 0; k < 4; k++) {
                // raw-value argmax; clip01 on scalar max below (inputs in
                // [0,1): elementwise clip is identity; strict > keeps
                // first-index semantics).
                int idx = (m * 32 + lane) * 4 + k;
                if (a[k] > gmax) { gmax = a[k]; gidx = idx; }
            }
        }

        // refill LDG pipe: batch c+1 in flight across the next iteration
        if (c + 1 < NGBATCH) {
#pragma unroll
            for (int i = 0; i < 8; i++) gv[i] = g4[((c + 1) * 8 + i) * 32 + lane];
        }
    }

    // ---- warp-wide masks via REDUX (uniform result in all lanes) ----
    const unsigned c15 = lane & 15;
    unsigned mcl = (c15 < 8)  ? (colnib << (c15 * 4))       : 0u;
    unsigned mch = (c15 >= 8) ? (colnib << ((c15 - 8) * 4)) : 0u;
    const unsigned cl = __reduce_or_sync(0xffffffffu, mcl);
    const unsigned ch = __reduce_or_sync(0xffffffffu, mch);
    const unsigned rl = __reduce_or_sync(0xffffffffu, rml);
    const unsigned rh = __reduce_or_sync(0xffffffffu, rmh);

    // ---- butterfly reductions: every lane ends with the warp result ----
#pragma unroll
    for (int o = 16; o; o >>= 1) {
        hmax = fmaxf(hmax, __shfl_xor_sync(0xffffffffu, hmax, o));
        float gv2 = __shfl_xor_sync(0xffffffffu, gmax, o);
        int   gi2 = __shfl_xor_sync(0xffffffffu, gidx, o);
        if (gv2 > gmax || (gv2 == gmax && gi2 < gidx)) { gmax = gv2; gidx = gi2; }
    }

    // ---- bbox (rare fallback: no pixel >= 0.5 -> head peak, warp-uniform) ----
    int x1, x2, y1, y2;
    if ((cl | ch) != 0u) {
        unsigned long long cm = ((unsigned long long)ch << 32) | cl;
        unsigned long long rm = ((unsigned long long)rh << 32) | rl;
        x1 = __ffsll((long long)cm) - 1;
        x2 = 64 - __clzll((long long)cm);
        y1 = __ffsll((long long)rm) - 1;
        y2 = 64 - __clzll((long long)rm);
    } else {
        const float4* h4 = reinterpret_cast<const float4*>(H + base);
        float pv = -1e30f; int pi = 0;
#pragma unroll 4
        for (int m = 0; m < 32; m++) {
            float4 v = h4[m * 32 + lane];          // rare reload (L2-hot)
            float a[4] = {v.x, v.y, v.z, v.w};
#pragma unroll
            for (int k = 0; k < 4; k++) {
                float hv = clip01(a[k]);
                int idx = (m * 32 + lane) * 4 + k;
                if (hv > pv) { pv = hv; pi = idx; }
            }
        }
#pragma unroll
        for (int o = 16; o; o >>= 1) {
            float v2 = __shfl_xor_sync(0xffffffffu, pv, o);
            int   i2 = __shfl_xor_sync(0xffffffffu, pi, o);
            if (v2 > pv || (v2 == pv && i2 < pi)) { pv = v2; pi = i2; }
        }
        int px = pi & 63, py = pi >> 6;
        x1 = px; x2 = px + 1; y1 = py; y2 = py + 1;
    }

    // ---- epilogue (warp-uniform; 10 connect samples on lanes 0-9) ----
    const float conf_head = clip01(hmax);
    const float conf_gaze = clip01(gmax);
    const float gpx = fminf(fmaxf((float)(gidx & 63), 0.0f), 63.0f);
    const float gpy = fminf(fmaxf((float)(gidx >> 6), 0.0f), 63.0f);
    const float cx = (float)(x1 + x2) * 0.5f;
    const float cy = (float)(y1 + y2) * 0.5f;
    // jnp.round == round-half-to-even == rintf (cx/cy hit .5 exactly)
    const float hcx = fminf(fmaxf(rintf(cx), 0.0f), 63.0f);
    const float hcy = fminf(fmaxf(rintf(cy), 0.0f), 63.0f);
    const float dx = gpx - hcx, dy = gpy - hcy;
    const float stx = dx / 9.0f, sty = dy / 9.0f;   // linspace step, num=10

    float samp = 0.0f;
    if (lane < 10) {
        int xi = (int)rintf(hcx + (float)lane * stx);
        int yi = (int)rintf(hcy + (float)lane * sty);
        samp = clip01(__ldg(C + base + yi * 64 + xi));
    }
#pragma unroll
    for (int o = 16; o; o >>= 1) samp += __shfl_xor_sync(0xffffffffu, samp, o);

    if (lane == 0) {
        float norm = sqrtf(dx * dx + dy * dy);
        float dp = fminf(32.0f / norm - 1.0f, 0.0f);  // norm==0 -> +inf -> 0
        float score = samp / 10.0f + dp;
        float watch = W[bq];
        float r = (watch > 0.5f)
                ? (conf_head + (1.0f - conf_gaze) - score)
                : (conf_head + conf_gaze + score);
        out[bq] = r / 3.0f;
    }
}

extern "C" void kernel_launch(void* const* d_in, const int* in_sizes, int n_in,
                              void* d_out, int out_size) {
    const float* G = (const float*)d_in[0];  // pred_gaze_heatmap
    const float* H = (const float*)d_in[1];  // pred_head_heatmap
    const float* C = (const float*)d_in[2];  // pred_connect_heatmap
    const float* W = (const float*)d_in[3];  // pred_gaze_watch_outside
    float* out = (float*)d_out;
    int n = in_sizes[3];                     // B*Q = 8192
    int grid = (n + WARPS_PER_BLOCK - 1) / WARPS_PER_BLOCK;   // 2048
    gotd_eval_kernel<<<grid, NTHR>>>(G, H, C, W, out, n);
}

// round 14
// speedup vs baseline: 1.5166x; 1.0108x over previous
#include <cuda_runtime.h>
#include <cuda_bf16.h>
#include <cstdint>

#define WARPS_PER_BLOCK 4
#define NTHR (32 * WARPS_PER_BLOCK)
#define CHUNK_BYTES 4096
#define CHUNK_F4 256               // float4 per 4 KB chunk
#define NCHUNK 8                   // 4 head + 4 gaze per bq
#define NBUF 3                     // ring depth per warp
#define LOOKAHEAD 3

__device__ __forceinline__ float clip01(float v) { return fminf(fmaxf(v, 0.0f), 1.0f); }

__device__ __forceinline__ void mbar_init(unsigned int mbar, unsigned int count) {
    asm volatile("mbarrier.init.shared.b64 [%0], %1;" :: "r"(mbar), "r"(count) : "memory");
}
__device__ __forceinline__ void tma_issue(unsigned int dst, const void* src, unsigned int mbar) {
    asm volatile("mbarrier.arrive.expect_tx.shared.b64 _, [%0], %1;"
                 :: "r"(mbar), "r"((unsigned int)CHUNK_BYTES) : "memory");
    asm volatile("cp.async.bulk.shared::cluster.global.mbarrier::complete_tx::bytes "
                 "[%0], [%1], %2, [%3];"
                 :: "r"(dst), "l"(src), "r"((unsigned int)CHUNK_BYTES), "r"(mbar) : "memory");
}
__device__ __forceinline__ void mbar_wait(unsigned int mbar, unsigned int parity) {
    unsigned int done;
    asm volatile("{\n\t.reg .pred p;\n\t"
                 "mbarrier.try_wait.parity.acquire.cta.shared::cta.b64 p, [%1], %2;\n\t"
                 "selp.b32 %0, 1, 0, p;\n\t}"
                 : "=r"(done) : "r"(mbar), "r"(parity) : "memory");
    while (!done) {
        asm volatile("{\n\t.reg .pred p;\n\t"
                     "mbarrier.try_wait.parity.acquire.cta.shared::cta.b64 p, [%1], %2;\n\t"
                     "selp.b32 %0, 1, 0, p;\n\t}"
                     : "=r"(done) : "r"(mbar), "r"(parity) : "memory");
    }
}

__global__ __launch_bounds__(NTHR)
void gotd_eval_kernel(const float* __restrict__ G,   // gaze heatmaps   [n,64,64]
                      const float* __restrict__ H,   // head heatmaps   [n,64,64]
                      const float* __restrict__ C,   // connect heatmaps[n,64,64]
                      const float* __restrict__ W,   // watch_outside   [n]
                      float* __restrict__ out, int n)
{
    // [warp][buf][256 float4] = 4*3*4KB = 48 KB; + per-warp mbarrier triple.
    __shared__ float4 sbuf[WARPS_PER_BLOCK * NBUF * CHUNK_F4];
    __shared__ unsigned long long smbar[WARPS_PER_BLOCK * NBUF];

    const int warp = threadIdx.x >> 5;
    const int lane = threadIdx.x & 31;
    const int bq = blockIdx.x * WARPS_PER_BLOCK + warp;

    float4* wbuf = &sbuf[warp * NBUF * CHUNK_F4];
    const unsigned int sbase = (unsigned int)__cvta_generic_to_shared(wbuf);
    const unsigned int mbase = (unsigned int)__cvta_generic_to_shared(&smbar[warp * NBUF]);

    // Per-warp init; no cross-warp coupling, no __syncthreads.
    if (lane == 0) {
#pragma unroll
        for (int b = 0; b < NBUF; b++) mbar_init(mbase + b * 8, 1);
        asm volatile("fence.proxy.async.shared::cta;" ::: "memory");
    }
    __syncwarp();
    if (bq >= n) return;

    const size_t base = (size_t)bq * 4096;
    const char* hsrc = reinterpret_cast<const char*>(H + base);
    const char* gsrc = reinterpret_cast<const char*>(G + base);

    // Chunk c: c<4 -> head bytes [c*4K,(c+1)*4K), else gaze [(c-4)*4K,...).
    auto chunk_src = [&](int c) -> const char* {
        return (c < 4) ? hsrc + c * CHUNK_BYTES : gsrc + (c - 4) * CHUNK_BYTES;
    };

    if (lane == 0) {
#pragma unroll
        for (int c = 0; c < LOOKAHEAD; c++)
            tma_issue(sbase + (c % NBUF) * CHUNK_BYTES, chunk_src(c), mbase + (c % NBUF) * 8);
    }

    // Per-lane layout (as R3): global slot s = m*32+lane; elem idx = s*4+k;
    // row = 2*m + (lane>>4); col = (lane&15)*4+k. Chunk c holds m in [8c',8c'+8).
    float hmax = -1e30f;
    unsigned colnib = 0;
    unsigned rml = 0, rmh = 0;
    float gmax = -1e30f; int gidx = 0;

#pragma unroll
    for (int c = 0; c < NCHUNK; c++) {
        const int b = c % NBUF;                 // buffer index
        mbar_wait(mbase + b * 8, (c / NBUF) & 1);   // uses: parity 0,1,0,...
        const float4* buf = wbuf + b * CHUNK_F4;

        // Pull all 8 float4 into registers FIRST, then free the buffer by
        // issuing the next TMA, then do the ALU consume (issue-early).
        float4 v[8];
#pragma unroll
        for (int i = 0; i < 8; i++) v[i] = buf[i * 32 + lane];

        if (c + LOOKAHEAD < NCHUNK) {
            __syncwarp();                        // all lanes have their regs
            if (lane == 0) {
                asm volatile("fence.proxy.async.shared::cta;" ::: "memory");
                tma_issue(sbase + b * CHUNK_BYTES, chunk_src(c + LOOKAHEAD), mbase + b * 8);
            }
        }

        if (c < 4) {
#pragma unroll
            for (int i = 0; i < 8; i++) {
                const int m = c * 8 + i;
                float a[4] = {v[i].x, v[i].y, v[i].z, v[i].w};
                bool any5 = false;
#pragma unroll
                for (int k = 0; k < 4; k++) {
                    hmax = fmaxf(hmax, a[k]);
                    if (a[k] >= 0.5f) { colnib |= 1u << k; any5 = true; }
                }
                if (any5) {
                    int row = 2 * m + (lane >> 4);
                    if (row < 32) rml |= 1u << row; else rmh |= 1u << (row - 32);
                }
            }
        } else {
#pragma unroll
            for (int i = 0; i < 8; i++) {
                const int m = (c - 4) * 8 + i;
                float a[4] = {v[i].x, v[i].y, v[i].z, v[i].w};
#pragma unroll
                for (int k = 0; k < 4; k++) {
                    // raw-value argmax; clip01 on scalar max below (inputs in
                    // [0,1): elementwise clip is identity; strict > keeps
                    // first-index semantics).
                    int idx = (m * 32 + lane) * 4 + k;
                    if (a[k] > gmax) { gmax = a[k]; gidx = idx; }
                }
            }
        }
    }

    // ---- warp-wide masks via REDUX (uniform result in all lanes) ----
    const unsigned c15 = lane & 15;
    unsigned mcl = (c15 < 8)  ? (colnib << (c15 * 4))       : 0u;
    unsigned mch = (c15 >= 8) ? (colnib << ((c15 - 8) * 4)) : 0u;
    const unsigned cl = __reduce_or_sync(0xffffffffu, mcl);
    const unsigned ch = __reduce_or_sync(0xffffffffu, mch);
    const unsigned rl = __reduce_or_sync(0xffffffffu, rml);
    const unsigned rh = __reduce_or_sync(0xffffffffu, rmh);

    // ---- butterfly reductions: every lane ends with the warp result ----
#pragma unroll
    for (int o = 16; o; o >>= 1) {
        hmax = fmaxf(hmax, __shfl_xor_sync(0xffffffffu, hmax, o));
        float gv2 = __shfl_xor_sync(0xffffffffu, gmax, o);
        int   gi2 = __shfl_xor_sync(0xffffffffu, gidx, o);
        if (gv2 > gmax || (gv2 == gmax && gi2 < gidx)) { gmax = gv2; gidx = gi2; }
    }

    // ---- bbox (rare fallback: no pixel >= 0.5 -> head peak, warp-uniform) ----
    int x1, x2, y1, y2;
    if ((cl | ch) != 0u) {
        unsigned long long cm = ((unsigned long long)ch << 32) | cl;
        unsigned long long rm = ((unsigned long long)rh << 32) | rl;
        x1 = __ffsll((long long)cm) - 1;
        x2 = 64 - __clzll((long long)cm);
        y1 = __ffsll((long long)rm) - 1;
        y2 = 64 - __clzll((long long)rm);
    } else {
        const float4* h4 = reinterpret_cast<const float4*>(H + base);
        float pv = -1e30f; int pi = 0;
#pragma unroll 4
        for (int m = 0; m < 32; m++) {
            float4 v = h4[m * 32 + lane];          // rare reload (L2-hot)
            float a[4] = {v.x, v.y, v.z, v.w};
#pragma unroll
            for (int k = 0; k < 4; k++) {
                float hv = clip01(a[k]);
                int idx = (m * 32 + lane) * 4 + k;
                if (hv > pv) { pv = hv; pi = idx; }
            }
        }
#pragma unroll
        for (int o = 16; o; o >>= 1) {
            float v2 = __shfl_xor_sync(0xffffffffu, pv, o);
            int   i2 = __shfl_xor_sync(0xffffffffu, pi, o);
            if (v2 > pv || (v2 == pv && i2 < pi)) { pv = v2; pi = i2; }
        }
        int px = pi & 63, py = pi >> 6;
        x1 = px; x2 = px + 1; y1 = py; y2 = py + 1;
    }

    // ---- epilogue (warp-uniform; 10 connect samples on lanes 0-9) ----
    const float conf_head = clip01(hmax);
    const float conf_gaze = clip01(gmax);
    const float gpx = fminf(fmaxf((float)(gidx & 63), 0.0f), 63.0f);
    const float gpy = fminf(fmaxf((float)(gidx >> 6), 0.0f), 63.0f);
    const float cx = (float)(x1 + x2) * 0.5f;
    const float cy = (float)(y1 + y2) * 0.5f;
    // jnp.round == round-half-to-even == rintf (cx/cy hit .5 exactly)
    const float hcx = fminf(fmaxf(rintf(cx), 0.0f), 63.0f);
    const float hcy = fminf(fmaxf(rintf(cy), 0.0f), 63.0f);
    const float dx = gpx - hcx, dy = gpy - hcy;
    const float stx = dx / 9.0f, sty = dy / 9.0f;   // linspace step, num=10

    float samp = 0.0f;
    if (lane < 10) {
        int xi = (int)rintf(hcx + (float)lane * stx);
        int yi = (int)rintf(hcy + (float)lane * sty);
        samp = clip01(__ldg(C + base + yi * 64 + xi));
    }
#pragma unroll
    for (int o = 16; o; o >>= 1) samp += __shfl_xor_sync(0xffffffffu, samp, o);

    if (lane == 0) {
        float norm = sqrtf(dx * dx + dy * dy);
        float dp = fminf(32.0f / norm - 1.0f, 0.0f);  // norm==0 -> +inf -> 0
        float score = samp / 10.0f + dp;
        float watch = W[bq];
        float r = (watch > 0.5f)
                ? (conf_head + (1.0f - conf_gaze) - score)
                : (conf_head + conf_gaze + score);
        out[bq] = r / 3.0f;
    }
}

extern "C" void kernel_launch(void* const* d_in, const int* in_sizes, int n_in,
                              void* d_out, int out_size) {
    const float* G = (const float*)d_in[0];  // pred_gaze_heatmap
    const float* H = (const float*)d_in[1];  // pred_head_heatmap
    const float* C = (const float*)d_in[2];  // pred_connect_heatmap
    const float* W = (const float*)d_in[3];  // pred_gaze_watch_outside
    float* out = (float*)d_out;
    int n = in_sizes[3];                     // B*Q = 8192
    int grid = (n + WARPS_PER_BLOCK - 1) / WARPS_PER_BLOCK;   // 2048
    gotd_eval_kernel<<<grid, NTHR>>>(G, H, C, W, out, n);
}